// round 4
// baseline (speedup 1.0000x reference)
#include <cuda_runtime.h>

// WindowOverlapProcessor: vectorized gather, two-wave loads + 64-reg cap.
// One thread per (b, h, 4-aligned w group). Boundary windows via clamp-index +
// zero-weight (all addresses valid, all loads unconditional). Loads split into
// two waves of 6 float4 (one per covering i-row) so live registers stay <=64
// -> 4 blocks/SM (occ 50%) while MLP=6 still covers DRAM latency.
// All address math in int32 (tensor is 24.4M floats < 2^31).

#define H_    512
#define W_    512
#define WS_   16
#define HW_   63
#define NW_   (HW_ * HW_)
#define B_    8
#define C_    3
#define PLANE (H_ * W_)

__global__ void __launch_bounds__(256, 4)
window_overlap_gather_v4c(const float* __restrict__ windows,
                          float* __restrict__ out)
{
    __shared__ float g[WS_];      // normalized 1D gaussian

    int tid = threadIdx.x;
    if (tid < WS_) {
        float x = (float)tid - 7.5f;
        g[tid] = expf(-(x * x) / 32.0f);
    }
    __syncthreads();
    if (tid == 0) {
        float s = 0.0f;
        #pragma unroll
        for (int k = 0; k < WS_; k++) s += g[k];
        float si = 1.0f / s;
        #pragma unroll
        for (int k = 0; k < WS_; k++) g[k] *= si;
    }
    __syncthreads();

    int gid = blockIdx.x * blockDim.x + tid;   // 0 .. B*H*(W/4)-1
    int w4 = (gid & 127) << 2;
    int h  = (gid >> 7) & 511;
    int b  = gid >> 16;

    int kh = h >> 3;
    int kw = w4 >> 3;

    // clamped window indices + validity
    int i0 = max(kh - 1, 0), i1 = min(kh, HW_ - 1);
    int j0 = max(kw - 1, 0), j1 = min(kw, HW_ - 1);
    bool vi0 = (kh - 1 >= 0), vi1 = (kh <= HW_ - 1);
    bool vj0 = (kw - 1 >= 0), vj1 = (kw <= HW_ - 1);

    int dh0 = h - (i0 << 3), dh1 = h - (i1 << 3);     // [0,15]
    int dwA = w4 - (j0 << 3), dwB = w4 - (j1 << 3);   // {0,4,8,12}

    // int32 offsets (in floats); max 24.4M < 2^31
    int bb = b * NW_;
    int o00 = 3 * ((((bb + i0 * HW_ + j0) << 8) + (dh0 << 4) + dwA));
    int o01 = 3 * ((((bb + i0 * HW_ + j1) << 8) + (dh0 << 4) + dwB));
    int o10 = 3 * ((((bb + i1 * HW_ + j0) << 8) + (dh1 << 4) + dwA));
    int o11 = 3 * ((((bb + i1 * HW_ + j1) << 8) + (dh1 << 4) + dwB));

    // weights
    float gh0 = vi0 ? g[dh0] : 0.0f;
    float gh1 = vi1 ? g[dh1] : 0.0f;
    float gwA0 = vj0 ? g[dwA]     : 0.0f;
    float gwA1 = vj0 ? g[dwA + 1] : 0.0f;
    float gwA2 = vj0 ? g[dwA + 2] : 0.0f;
    float gwA3 = vj0 ? g[dwA + 3] : 0.0f;
    float gwB0 = vj1 ? g[dwB]     : 0.0f;
    float gwB1 = vj1 ? g[dwB + 1] : 0.0f;
    float gwB2 = vj1 ? g[dwB + 2] : 0.0f;
    float gwB3 = vj1 ? g[dwB + 3] : 0.0f;

    float sh = gh0 + gh1;
    float inv0 = 1.0f / (sh * (gwA0 + gwB0) + 1e-8f);
    float inv1 = 1.0f / (sh * (gwA1 + gwB1) + 1e-8f);
    float inv2 = 1.0f / (sh * (gwA2 + gwB2) + 1e-8f);
    float inv3 = 1.0f / (sh * (gwA3 + gwB3) + 1e-8f);

    float a00, a01, a02, a10, a11, a12, a20, a21, a22, a30, a31, a32;

    // ---- wave 1: i-row 0 (windows (i0,j0) and (i0,j1)), 6x LDG.128 ----
    {
        const float4* pA = (const float4*)(windows + o00);
        const float4* pB = (const float4*)(windows + o01);
        float4 vAa = pA[0], vAb = pA[1], vAc = pA[2];
        float4 vBa = pB[0], vBb = pB[1], vBc = pB[2];

        float w0 = gh0 * gwA0, w1 = gh0 * gwA1, w2 = gh0 * gwA2, w3 = gh0 * gwA3;
        a00 = w0 * vAa.x; a01 = w0 * vAa.y; a02 = w0 * vAa.z;
        a10 = w1 * vAa.w; a11 = w1 * vAb.x; a12 = w1 * vAb.y;
        a20 = w2 * vAb.z; a21 = w2 * vAb.w; a22 = w2 * vAc.x;
        a30 = w3 * vAc.y; a31 = w3 * vAc.z; a32 = w3 * vAc.w;

        w0 = gh0 * gwB0; w1 = gh0 * gwB1; w2 = gh0 * gwB2; w3 = gh0 * gwB3;
        a00 += w0 * vBa.x; a01 += w0 * vBa.y; a02 += w0 * vBa.z;
        a10 += w1 * vBa.w; a11 += w1 * vBb.x; a12 += w1 * vBb.y;
        a20 += w2 * vBb.z; a21 += w2 * vBb.w; a22 += w2 * vBc.x;
        a30 += w3 * vBc.y; a31 += w3 * vBc.z; a32 += w3 * vBc.w;
    }

    // ---- wave 2: i-row 1 (windows (i1,j0) and (i1,j1)), 6x LDG.128 ----
    {
        const float4* pA = (const float4*)(windows + o10);
        const float4* pB = (const float4*)(windows + o11);
        float4 vAa = pA[0], vAb = pA[1], vAc = pA[2];
        float4 vBa = pB[0], vBb = pB[1], vBc = pB[2];

        float w0 = gh1 * gwA0, w1 = gh1 * gwA1, w2 = gh1 * gwA2, w3 = gh1 * gwA3;
        a00 += w0 * vAa.x; a01 += w0 * vAa.y; a02 += w0 * vAa.z;
        a10 += w1 * vAa.w; a11 += w1 * vAb.x; a12 += w1 * vAb.y;
        a20 += w2 * vAb.z; a21 += w2 * vAb.w; a22 += w2 * vAc.x;
        a30 += w3 * vAc.y; a31 += w3 * vAc.z; a32 += w3 * vAc.w;

        w0 = gh1 * gwB0; w1 = gh1 * gwB1; w2 = gh1 * gwB2; w3 = gh1 * gwB3;
        a00 += w0 * vBa.x; a01 += w0 * vBa.y; a02 += w0 * vBa.z;
        a10 += w1 * vBa.w; a11 += w1 * vBb.x; a12 += w1 * vBb.y;
        a20 += w2 * vBb.z; a21 += w2 * vBb.w; a22 += w2 * vBc.x;
        a30 += w3 * vBc.y; a31 += w3 * vBc.z; a32 += w3 * vBc.w;
    }

    float* ob = out + b * (C_ * PLANE) + (h << 9) + w4;
    *(float4*)(ob)           = make_float4(a00 * inv0, a10 * inv1, a20 * inv2, a30 * inv3);
    *(float4*)(ob + PLANE)   = make_float4(a01 * inv0, a11 * inv1, a21 * inv2, a31 * inv3);
    *(float4*)(ob + 2*PLANE) = make_float4(a02 * inv0, a12 * inv1, a22 * inv2, a32 * inv3);
}

extern "C" void kernel_launch(void* const* d_in, const int* in_sizes, int n_in,
                              void* d_out, int out_size)
{
    const float* windows = (const float*)d_in[0];
    float* out = (float*)d_out;
    int total = B_ * H_ * (W_ / 4);   // 524288 threads
    window_overlap_gather_v4c<<<total / 256, 256>>>(windows, out);
}

// round 5
// speedup vs baseline: 1.0090x; 1.0090x over previous
#include <cuda_runtime.h>

// WindowOverlapProcessor: vectorized gather, single 12-load wave, 128-thr blocks.
// One thread per (b, h, 4-aligned w group). Boundary windows via clamp-index +
// zero-weight -> all 12 LDG.128 unconditional and front-batched (MLP=12).
// __launch_bounds__(128, 7): reg cap 73 (== what this body needs, no spill)
// but 7 blocks/SM = 28 warps instead of 24 -> +17% in-flight bytes.
// All address math int32 (windows tensor is 24.4M floats < 2^31).

#define H_    512
#define W_    512
#define WS_   16
#define HW_   63
#define NW_   (HW_ * HW_)
#define B_    8
#define C_    3
#define PLANE (H_ * W_)

__global__ void __launch_bounds__(128, 7)
window_overlap_gather_v4d(const float* __restrict__ windows,
                          float* __restrict__ out)
{
    __shared__ float g[WS_];      // normalized 1D gaussian

    int tid = threadIdx.x;
    if (tid < WS_) {
        float x = (float)tid - 7.5f;
        g[tid] = expf(-(x * x) / 32.0f);
    }
    __syncthreads();
    if (tid == 0) {
        float s = 0.0f;
        #pragma unroll
        for (int k = 0; k < WS_; k++) s += g[k];
        float si = 1.0f / s;
        #pragma unroll
        for (int k = 0; k < WS_; k++) g[k] *= si;
    }
    __syncthreads();

    int gid = blockIdx.x * 128 + tid;          // 0 .. B*H*(W/4)-1
    int w4 = (gid & 127) << 2;
    int h  = (gid >> 7) & 511;
    int b  = gid >> 16;

    int kh = h >> 3;
    int kw = w4 >> 3;

    // clamped window indices + validity
    int i0 = max(kh - 1, 0), i1 = min(kh, HW_ - 1);
    int j0 = max(kw - 1, 0), j1 = min(kw, HW_ - 1);
    bool vi0 = (kh - 1 >= 0), vi1 = (kh <= HW_ - 1);
    bool vj0 = (kw - 1 >= 0), vj1 = (kw <= HW_ - 1);

    int dh0 = h - (i0 << 3), dh1 = h - (i1 << 3);     // [0,15]
    int dwA = w4 - (j0 << 3), dwB = w4 - (j1 << 3);   // {0,4,8,12}

    // int32 float-offsets (max ~24.4M < 2^31)
    int bb = b * NW_;
    int o00 = 3 * (((bb + i0 * HW_ + j0) << 8) + (dh0 << 4) + dwA);
    int o01 = 3 * (((bb + i0 * HW_ + j1) << 8) + (dh0 << 4) + dwB);
    int o10 = 3 * (((bb + i1 * HW_ + j0) << 8) + (dh1 << 4) + dwA);
    int o11 = 3 * (((bb + i1 * HW_ + j1) << 8) + (dh1 << 4) + dwB);

    // ---- front-batched loads: 4 windows x 3 float4, no control deps ----
    const float4* p00 = (const float4*)(windows + o00);
    const float4* p01 = (const float4*)(windows + o01);
    const float4* p10 = (const float4*)(windows + o10);
    const float4* p11 = (const float4*)(windows + o11);

    float4 v00a = p00[0], v00b = p00[1], v00c = p00[2];
    float4 v01a = p01[0], v01b = p01[1], v01c = p01[2];
    float4 v10a = p10[0], v10b = p10[1], v10c = p10[2];
    float4 v11a = p11[0], v11b = p11[1], v11c = p11[2];

    // ---- weights (overlaps load latency) ----
    float gh0 = vi0 ? g[dh0] : 0.0f;
    float gh1 = vi1 ? g[dh1] : 0.0f;
    float gwA0 = vj0 ? g[dwA]     : 0.0f;
    float gwA1 = vj0 ? g[dwA + 1] : 0.0f;
    float gwA2 = vj0 ? g[dwA + 2] : 0.0f;
    float gwA3 = vj0 ? g[dwA + 3] : 0.0f;
    float gwB0 = vj1 ? g[dwB]     : 0.0f;
    float gwB1 = vj1 ? g[dwB + 1] : 0.0f;
    float gwB2 = vj1 ? g[dwB + 2] : 0.0f;
    float gwB3 = vj1 ? g[dwB + 3] : 0.0f;

    float sh = gh0 + gh1;
    float inv0 = 1.0f / (sh * (gwA0 + gwB0) + 1e-8f);
    float inv1 = 1.0f / (sh * (gwA1 + gwB1) + 1e-8f);
    float inv2 = 1.0f / (sh * (gwA2 + gwB2) + 1e-8f);
    float inv3 = 1.0f / (sh * (gwA3 + gwB3) + 1e-8f);

    // ---- accumulate: 4 px x 3 ch ----
    // layout per window: vXa={p0c0,p0c1,p0c2,p1c0} vXb={p1c1,p1c2,p2c0,p2c1}
    //                    vXc={p2c2,p3c0,p3c1,p3c2}
    float a00, a01, a02, a10, a11, a12, a20, a21, a22, a30, a31, a32;
    {
        float w0 = gh0 * gwA0, w1 = gh0 * gwA1, w2 = gh0 * gwA2, w3 = gh0 * gwA3;
        a00 = w0 * v00a.x; a01 = w0 * v00a.y; a02 = w0 * v00a.z;
        a10 = w1 * v00a.w; a11 = w1 * v00b.x; a12 = w1 * v00b.y;
        a20 = w2 * v00b.z; a21 = w2 * v00b.w; a22 = w2 * v00c.x;
        a30 = w3 * v00c.y; a31 = w3 * v00c.z; a32 = w3 * v00c.w;
    }
    {
        float w0 = gh0 * gwB0, w1 = gh0 * gwB1, w2 = gh0 * gwB2, w3 = gh0 * gwB3;
        a00 += w0 * v01a.x; a01 += w0 * v01a.y; a02 += w0 * v01a.z;
        a10 += w1 * v01a.w; a11 += w1 * v01b.x; a12 += w1 * v01b.y;
        a20 += w2 * v01b.z; a21 += w2 * v01b.w; a22 += w2 * v01c.x;
        a30 += w3 * v01c.y; a31 += w3 * v01c.z; a32 += w3 * v01c.w;
    }
    {
        float w0 = gh1 * gwA0, w1 = gh1 * gwA1, w2 = gh1 * gwA2, w3 = gh1 * gwA3;
        a00 += w0 * v10a.x; a01 += w0 * v10a.y; a02 += w0 * v10a.z;
        a10 += w1 * v10a.w; a11 += w1 * v10b.x; a12 += w1 * v10b.y;
        a20 += w2 * v10b.z; a21 += w2 * v10b.w; a22 += w2 * v10c.x;
        a30 += w3 * v10c.y; a31 += w3 * v10c.z; a32 += w3 * v10c.w;
    }
    {
        float w0 = gh1 * gwB0, w1 = gh1 * gwB1, w2 = gh1 * gwB2, w3 = gh1 * gwB3;
        a00 += w0 * v11a.x; a01 += w0 * v11a.y; a02 += w0 * v11a.z;
        a10 += w1 * v11a.w; a11 += w1 * v11b.x; a12 += w1 * v11b.y;
        a20 += w2 * v11b.z; a21 += w2 * v11b.w; a22 += w2 * v11c.x;
        a30 += w3 * v11c.y; a31 += w3 * v11c.z; a32 += w3 * v11c.w;
    }

    float* ob = out + b * (C_ * PLANE) + (h << 9) + w4;
    *(float4*)(ob)           = make_float4(a00 * inv0, a10 * inv1, a20 * inv2, a30 * inv3);
    *(float4*)(ob + PLANE)   = make_float4(a01 * inv0, a11 * inv1, a21 * inv2, a31 * inv3);
    *(float4*)(ob + 2*PLANE) = make_float4(a02 * inv0, a12 * inv1, a22 * inv2, a32 * inv3);
}

extern "C" void kernel_launch(void* const* d_in, const int* in_sizes, int n_in,
                              void* d_out, int out_size)
{
    const float* windows = (const float*)d_in[0];
    float* out = (float*)d_out;
    int total = B_ * H_ * (W_ / 4);   // 524288 threads
    window_overlap_gather_v4d<<<total / 128, 128>>>(windows, out);
}

// round 6
// speedup vs baseline: 1.0769x; 1.0673x over previous
#include <cuda_runtime.h>

// WindowOverlapProcessor: smem-staged coalesced gather.
// Block = (b, even row-pair h0..h0+1, 256-px w-slab). The 4 covering windows
// per pixel come from 2 window-rows x 33 windows; each window contributes 2
// contiguous, 128B-aligned rows (384B chunk). Chunks staged to smem with
// cp.async (coalesced global reads, ~4 wf/instr instead of ~16), consumers
// gather with conflict-free LDS.128 (chunk stride padded to 416B).
// Boundary windows: clamp-index + zero-weight.

#define HW_    63
#define NW_    (HW_ * HW_)
#define B_     8
#define PLANE  (512 * 512)

#define CHUNK_F4 26            // 24 used + 2 pad (416B stride)
#define NCHUNK   66            // 2 i-rows x 33 j-windows
#define STAGE_F4 (NCHUNK * CHUNK_F4)
#define STAGE_ELEMS 1584       // 66 * 24 useful float4

__global__ void __launch_bounds__(128, 8)
wop_staged(const float* __restrict__ windows, float* __restrict__ out)
{
    __shared__ float4 stage[STAGE_F4];   // 27456 B
    __shared__ float  g[16];

    int tid = threadIdx.x;
    int bx  = blockIdx.x;
    int wslab = bx & 1;                  // 0/1 -> w in [0,256)/[256,512)
    int hpair = (bx >> 1) & 255;
    int b     = bx >> 9;
    int h0 = hpair << 1;                 // even
    int w0 = wslab << 8;

    int kh   = h0 >> 3;
    int i0cl = max(kh - 1, 0);
    int i1cl = min(kh, HW_ - 1);
    int dA   = h0 - (i0cl << 3);         // base dh row in window i0cl (even, <=14)
    int dB   = h0 - (i1cl << 3);
    int jbase = (w0 >> 3) - 1;
    int bNW  = b * NW_;

    // ---- stage 66 chunks x 24 float4 via cp.async (coalesced) ----
    unsigned sb = (unsigned)__cvta_generic_to_shared(stage);
    for (int s = tid; s < STAGE_ELEMS; s += 128) {
        int chunk  = s / 24;
        int within = s - chunk * 24;
        int ii = (chunk >= 33) ? 1 : 0;
        int u  = chunk - (ii ? 33 : 0);
        int j  = min(max(jbase + u, 0), HW_ - 1);
        int iw = ii ? i1cl : i0cl;
        int dd = ii ? dB : dA;
        // window = 768 floats = 192 float4; row dd -> dd*12 f4; 24 f4 = 2 rows
        int gsrc = (bNW + iw * HW_ + j) * 192 + dd * 12 + within;
        unsigned dst = sb + (unsigned)((chunk * CHUNK_F4 + within) << 4);
        const float4* src = ((const float4*)windows) + gsrc;
        asm volatile("cp.async.cg.shared.global [%0], [%1], 16;"
                     :: "r"(dst), "l"(src) : "memory");
    }
    asm volatile("cp.async.commit_group;" ::: "memory");

    // ---- gaussian table (overlaps the async copies) ----
    if (tid < 16) { float x = (float)tid - 7.5f; g[tid] = expf(-(x * x) / 32.0f); }
    __syncthreads();
    if (tid == 0) {
        float ssum = 0.0f;
        #pragma unroll
        for (int k = 0; k < 16; k++) ssum += g[k];
        float si = 1.0f / ssum;
        #pragma unroll
        for (int k = 0; k < 16; k++) g[k] *= si;
    }
    asm volatile("cp.async.wait_group 0;" ::: "memory");
    __syncthreads();

    // ---- consumer: thread = (row r, w4 group) ----
    int r     = tid >> 6;
    int w4loc = (tid & 63) << 2;
    int w4 = w0 + w4loc;
    int h  = h0 + r;
    int kw = w4 >> 3;
    int u0 = w4loc >> 3;                 // chunk col of window kw-1; u0+1 -> kw
    int dwA = (w4 & 7) + 8;              // {8,12}  (window kw-1)
    int dwB = w4 & 7;                    // {0,4}   (window kw)

    bool vi0 = (kh >= 1),  vi1 = (kh <= HW_ - 1);
    bool vj0 = (kw >= 1),  vj1 = (kw <= HW_ - 1);

    float gh0 = vi0 ? g[(h & 7) + 8] : 0.0f;
    float gh1 = vi1 ? g[h & 7]       : 0.0f;
    float gwA0 = vj0 ? g[dwA]     : 0.0f;
    float gwA1 = vj0 ? g[dwA + 1] : 0.0f;
    float gwA2 = vj0 ? g[dwA + 2] : 0.0f;
    float gwA3 = vj0 ? g[dwA + 3] : 0.0f;
    float gwB0 = vj1 ? g[dwB]     : 0.0f;
    float gwB1 = vj1 ? g[dwB + 1] : 0.0f;
    float gwB2 = vj1 ? g[dwB + 2] : 0.0f;
    float gwB3 = vj1 ? g[dwB + 3] : 0.0f;

    float sh = gh0 + gh1;
    float inv0 = 1.0f / (sh * (gwA0 + gwB0) + 1e-8f);
    float inv1 = 1.0f / (sh * (gwA1 + gwB1) + 1e-8f);
    float inv2 = 1.0f / (sh * (gwA2 + gwB2) + 1e-8f);
    float inv3 = 1.0f / (sh * (gwA3 + gwB3) + 1e-8f);

    // smem float4 bases: chunk (ii,u), row r (12 f4), dw -> dw*3/4 f4
    int rowoff = r * 12;
    int fA = (dwA * 3) >> 2;             // 6 or 9
    int fB = (dwB * 3) >> 2;             // 0 or 3
    int c00 = (u0)      * CHUNK_F4 + rowoff + fA;   // (i0, kw-1)
    int c01 = (u0 + 1)  * CHUNK_F4 + rowoff + fB;   // (i0, kw)
    int c10 = (33 + u0) * CHUNK_F4 + rowoff + fA;   // (i1, kw-1)
    int c11 = (34 + u0) * CHUNK_F4 + rowoff + fB;   // (i1, kw)

    float a00, a01, a02, a10, a11, a12, a20, a21, a22, a30, a31, a32;
    // layout per 3-float4 group: v_a={p0c0,p0c1,p0c2,p1c0} v_b={p1c1,p1c2,p2c0,p2c1}
    //                            v_c={p2c2,p3c0,p3c1,p3c2}
    {
        float4 va = stage[c00], vb = stage[c00 + 1], vc = stage[c00 + 2];
        float q0 = gh0 * gwA0, q1 = gh0 * gwA1, q2 = gh0 * gwA2, q3 = gh0 * gwA3;
        a00 = q0 * va.x; a01 = q0 * va.y; a02 = q0 * va.z;
        a10 = q1 * va.w; a11 = q1 * vb.x; a12 = q1 * vb.y;
        a20 = q2 * vb.z; a21 = q2 * vb.w; a22 = q2 * vc.x;
        a30 = q3 * vc.y; a31 = q3 * vc.z; a32 = q3 * vc.w;
    }
    {
        float4 va = stage[c01], vb = stage[c01 + 1], vc = stage[c01 + 2];
        float q0 = gh0 * gwB0, q1 = gh0 * gwB1, q2 = gh0 * gwB2, q3 = gh0 * gwB3;
        a00 += q0 * va.x; a01 += q0 * va.y; a02 += q0 * va.z;
        a10 += q1 * va.w; a11 += q1 * vb.x; a12 += q1 * vb.y;
        a20 += q2 * vb.z; a21 += q2 * vb.w; a22 += q2 * vc.x;
        a30 += q3 * vc.y; a31 += q3 * vc.z; a32 += q3 * vc.w;
    }
    {
        float4 va = stage[c10], vb = stage[c10 + 1], vc = stage[c10 + 2];
        float q0 = gh1 * gwA0, q1 = gh1 * gwA1, q2 = gh1 * gwA2, q3 = gh1 * gwA3;
        a00 += q0 * va.x; a01 += q0 * va.y; a02 += q0 * va.z;
        a10 += q1 * va.w; a11 += q1 * vb.x; a12 += q1 * vb.y;
        a20 += q2 * vb.z; a21 += q2 * vb.w; a22 += q2 * vc.x;
        a30 += q3 * vc.y; a31 += q3 * vc.z; a32 += q3 * vc.w;
    }
    {
        float4 va = stage[c11], vb = stage[c11 + 1], vc = stage[c11 + 2];
        float q0 = gh1 * gwB0, q1 = gh1 * gwB1, q2 = gh1 * gwB2, q3 = gh1 * gwB3;
        a00 += q0 * va.x; a01 += q0 * va.y; a02 += q0 * va.z;
        a10 += q1 * va.w; a11 += q1 * vb.x; a12 += q1 * vb.y;
        a20 += q2 * vb.z; a21 += q2 * vb.w; a22 += q2 * vc.x;
        a30 += q3 * vc.y; a31 += q3 * vc.z; a32 += q3 * vc.w;
    }

    float* ob = out + b * (3 * PLANE) + (h << 9) + w4;
    *(float4*)(ob)             = make_float4(a00 * inv0, a10 * inv1, a20 * inv2, a30 * inv3);
    *(float4*)(ob + PLANE)     = make_float4(a01 * inv0, a11 * inv1, a21 * inv2, a31 * inv3);
    *(float4*)(ob + 2 * PLANE) = make_float4(a02 * inv0, a12 * inv1, a22 * inv2, a32 * inv3);
}

extern "C" void kernel_launch(void* const* d_in, const int* in_sizes, int n_in,
                              void* d_out, int out_size)
{
    const float* windows = (const float*)d_in[0];
    float* out = (float*)d_out;
    // blocks: 8 b x 256 h-pairs x 2 w-slabs = 4096
    wop_staged<<<4096, 128>>>(windows, out);
}